// round 1
// baseline (speedup 1.0000x reference)
#include <cuda_runtime.h>
#include <cuda_bf16.h>
#include <cstdint>
#include <cstddef>

// ---------------------------------------------------------------------------
// Problem constants
// ---------------------------------------------------------------------------
#define BB   128      // batch
#define DD   512      // d_model
#define HH   8        // heads
#define LL   6        // layers
#define SS   200      // seq len
#define LAT  256
#define OUTD 6
#define DKH  64       // DD/HH
#define DFF  2048
#define NTOK (BB*SS)  // 25600

// ---------------------------------------------------------------------------
// Device scratch (allocation-free rule: __device__ globals)
// ---------------------------------------------------------------------------
__device__ __align__(256) float g_x  [NTOK*DD];
__device__ __align__(256) float g_q  [NTOK*DD];
__device__ __align__(256) float g_k  [NTOK*DD];
__device__ __align__(256) float g_v  [NTOK*DD];
__device__ __align__(256) float g_ctx[NTOK*DD];
__device__ __align__(256) float g_tmp[NTOK*DD];
__device__ __align__(256) float g_h1 [NTOK*DFF];
__device__ __align__(256) float g_t1 [NTOK*(DD/2)];
__device__ __align__(256) float g_z  [BB*LAT];
__device__ __align__(256) float g_s1 [BB*(DD/2)];

// ---------------------------------------------------------------------------
// Helpers
// ---------------------------------------------------------------------------
__device__ __forceinline__ float gelu_f(float x) {
    return 0.5f * x * (1.0f + erff(x * 0.7071067811865475f));
}

__device__ __forceinline__ unsigned long long pk2(float x, float y) {
    unsigned long long r;
    asm("mov.b64 %0, {%1, %2};" : "=l"(r) : "f"(x), "f"(y));
    return r;
}
__device__ __forceinline__ void upk2(unsigned long long v, float& x, float& y) {
    asm("mov.b64 {%0, %1}, %2;" : "=f"(x), "=f"(y) : "l"(v));
}
// packed fp32x2 FMA (FFMA2) — sm_103a, 2 FMA per instruction
__device__ __forceinline__ void fma2(unsigned long long& c, unsigned long long a,
                                     unsigned long long b) {
    asm("fma.rn.f32x2 %0, %1, %2, %3;" : "=l"(c) : "l"(a), "l"(b), "l"(c));
}

// ---------------------------------------------------------------------------
// SGEMM: C[M,N] = act(A[M,K] @ B[K,N] + bias[N])
// Requirements (all satisfied by every call site):
//   M % 128 == 0, N % 128 == 0, K % 8 == 0
// 128x128x8 tile, 256 threads, 8x8 per-thread microtile as 8x4 f32x2 pairs.
// ACT: 0 = none, 1 = exact GELU
// ---------------------------------------------------------------------------
template <int ACT>
__global__ __launch_bounds__(256) void sgemm_kernel(
    int M, int N, int K,
    const float* __restrict__ A, const float* __restrict__ B,
    const float* __restrict__ bias, float* __restrict__ C)
{
    __shared__ float As[8][128];   // transposed: As[k][m]
    __shared__ float Bs[8][128];

    const int tid = threadIdx.x;
    const int bx = blockIdx.x;     // N tile
    const int by = blockIdx.y;     // M tile
    const int tr = tid >> 4;       // 0..15
    const int tc = tid & 15;       // 0..15
    const int a_row = tid >> 1;          // 0..127
    const int a_col = (tid & 1) << 2;    // 0 or 4
    const int b_row = tid >> 5;          // 0..7
    const int b_col = (tid & 31) << 2;   // 0..124

    const float* Ab = A + (size_t)by * 128 * K;
    const float* Bb = B + (size_t)bx * 128;

    unsigned long long acc[8][4];
#pragma unroll
    for (int i = 0; i < 8; i++)
#pragma unroll
        for (int j = 0; j < 4; j++) acc[i][j] = 0ULL;

    for (int k0 = 0; k0 < K; k0 += 8) {
        float4 av = *(const float4*)(Ab + (size_t)a_row * K + k0 + a_col);
        As[a_col + 0][a_row] = av.x;
        As[a_col + 1][a_row] = av.y;
        As[a_col + 2][a_row] = av.z;
        As[a_col + 3][a_row] = av.w;
        float4 bv = *(const float4*)(Bb + (size_t)(k0 + b_row) * N + b_col);
        *(float4*)&Bs[b_row][b_col] = bv;
        __syncthreads();
#pragma unroll
        for (int kk = 0; kk < 8; kk++) {
            unsigned long long ap[8];
#pragma unroll
            for (int i = 0; i < 8; i++) {
                float a_ = As[kk][tr * 8 + i];
                ap[i] = pk2(a_, a_);
            }
            unsigned long long bp[4];
            const unsigned long long* b2 =
                (const unsigned long long*)&Bs[kk][tc * 8];
#pragma unroll
            for (int j = 0; j < 4; j++) bp[j] = b2[j];
#pragma unroll
            for (int i = 0; i < 8; i++)
#pragma unroll
                for (int j = 0; j < 4; j++) fma2(acc[i][j], ap[i], bp[j]);
        }
        __syncthreads();
    }

    const int row0 = by * 128 + tr * 8;
    const int col0 = bx * 128 + tc * 8;
#pragma unroll
    for (int i = 0; i < 8; i++) {
        float out[8];
#pragma unroll
        for (int j = 0; j < 4; j++) {
            float x, y;
            upk2(acc[i][j], x, y);
            x += bias[col0 + 2 * j];
            y += bias[col0 + 2 * j + 1];
            if (ACT == 1) { x = gelu_f(x); y = gelu_f(y); }
            out[2 * j]     = x;
            out[2 * j + 1] = y;
        }
        float4* crow = (float4*)(C + (size_t)(row0 + i) * N + col0);
        crow[0] = make_float4(out[0], out[1], out[2], out[3]);
        crow[1] = make_float4(out[4], out[5], out[6], out[7]);
    }
}

// ---------------------------------------------------------------------------
// concat z = [z_style | z_skill]  -> [B, 256]
// ---------------------------------------------------------------------------
__global__ void concat_z_kernel(const float* __restrict__ zs,
                                const float* __restrict__ zk,
                                float* __restrict__ z)
{
    int i = blockIdx.x * blockDim.x + threadIdx.x;
    if (i >= BB * LAT) return;
    int b = i >> 8, c = i & 255;
    z[i] = (c < 128) ? zs[b * 128 + c] : zk[b * 128 + (c - 128)];
}

// ---------------------------------------------------------------------------
// x[b,s,d] += PE(s,d) (sinusoidal)
// ---------------------------------------------------------------------------
__global__ void add_pe_kernel(float* __restrict__ x)
{
    int idx = blockIdx.x * blockDim.x + threadIdx.x;
    if (idx >= NTOK * DD) return;
    int d = idx & (DD - 1);
    int s = (idx >> 9) % SS;
    const float c = -9.210340371976184f / (float)DD;   // -ln(10000)/D
    int de = d & ~1;
    float div = expf((float)de * c);
    float ang = (float)s * div;
    x[idx] += (d & 1) ? cosf(ang) : sinf(ang);
}

// ---------------------------------------------------------------------------
// Fused attention for one (b, h, 25-row i-tile).
// grid = (8, H, B), block = 256.
// Q/K/V laid out [B,S,H*DK] (i.e. [B,S,D] with head-major columns).
// ---------------------------------------------------------------------------
__global__ __launch_bounds__(256) void attn_kernel(
    const float* __restrict__ Q, const float* __restrict__ Km,
    const float* __restrict__ Vm, const float* __restrict__ bias,
    float* __restrict__ O)
{
    __shared__ float q_sm[25][65];
    __shared__ float kv_sm[50][65];
    __shared__ float sc[25][200];

    const int it  = blockIdx.x;     // 0..7  (25 rows each)
    const int h   = blockIdx.y;
    const int b   = blockIdx.z;
    const int tid = threadIdx.x;
    const int i0  = it * 25;
    const size_t base = (size_t)b * SS * DD + (size_t)h * DKH;

    for (int p = tid; p < 25 * 64; p += 256) {
        int i = p >> 6, d = p & 63;
        q_sm[i][d] = Q[base + (size_t)(i0 + i) * DD + d];
    }

    // --- scores = QK^T/8 + bias ---
    for (int jt = 0; jt < 4; jt++) {
        int j0 = jt * 50;
        __syncthreads();
        for (int p = tid; p < 50 * 64; p += 256) {
            int j = p >> 6, d = p & 63;
            kv_sm[j][d] = Km[base + (size_t)(j0 + j) * DD + d];
        }
        __syncthreads();
        for (int p = tid; p < 25 * 50; p += 256) {
            int i = p / 50, j = p - i * 50;
            float s = 0.f;
#pragma unroll 16
            for (int d = 0; d < 64; d++) s += q_sm[i][d] * kv_sm[j][d];
            sc[i][j0 + j] = s * 0.125f +
                bias[((size_t)h * SS + (i0 + i)) * SS + (j0 + j)];
        }
    }
    __syncthreads();

    // --- softmax (warp per row) ---
    const int wid = tid >> 5, lane = tid & 31;
    for (int i = wid; i < 25; i += 8) {
        float m = -1e30f;
        for (int j = lane; j < SS; j += 32) m = fmaxf(m, sc[i][j]);
#pragma unroll
        for (int o = 16; o > 0; o >>= 1)
            m = fmaxf(m, __shfl_xor_sync(0xffffffffu, m, o));
        float sum = 0.f;
        for (int j = lane; j < SS; j += 32) {
            float e = expf(sc[i][j] - m);
            sc[i][j] = e;
            sum += e;
        }
#pragma unroll
        for (int o = 16; o > 0; o >>= 1)
            sum += __shfl_xor_sync(0xffffffffu, sum, o);
        float inv = 1.f / sum;
        for (int j = lane; j < SS; j += 32) sc[i][j] *= inv;
    }

    // --- ctx = softmax @ V ---
    float acc[7] = {0.f, 0.f, 0.f, 0.f, 0.f, 0.f, 0.f};
    for (int jt = 0; jt < 4; jt++) {
        int j0 = jt * 50;
        __syncthreads();
        for (int p = tid; p < 50 * 64; p += 256) {
            int j = p >> 6, d = p & 63;
            kv_sm[j][d] = Vm[base + (size_t)(j0 + j) * DD + d];
        }
        __syncthreads();
#pragma unroll
        for (int r = 0; r < 7; r++) {
            int p = tid + r * 256;
            if (p < 25 * 64) {
                int i = p >> 6, d = p & 63;
                float a = acc[r];
#pragma unroll 10
                for (int jj = 0; jj < 50; jj++)
                    a += sc[i][j0 + jj] * kv_sm[jj][d];
                acc[r] = a;
            }
        }
    }
#pragma unroll
    for (int r = 0; r < 7; r++) {
        int p = tid + r * 256;
        if (p < 25 * 64) {
            int i = p >> 6, d = p & 63;
            O[base + (size_t)(i0 + i) * DD + d] = acc[r];
        }
    }
}

// ---------------------------------------------------------------------------
// x = LayerNorm(x + res) * g + be   (in place on x). One block per row.
// ---------------------------------------------------------------------------
__global__ __launch_bounds__(128) void ln_kernel(
    float* __restrict__ x, const float* __restrict__ res,
    const float* __restrict__ g, const float* __restrict__ be)
{
    const int row = blockIdx.x;
    float* xr = x + (size_t)row * DD;
    const float* rr = res + (size_t)row * DD;
    const int tid = threadIdx.x;

    float v[4];
    float s = 0.f;
#pragma unroll
    for (int i = 0; i < 4; i++) {
        int c = tid + i * 128;
        v[i] = xr[c] + rr[c];
        s += v[i];
    }
    __shared__ float red1[4];
    __shared__ float red2[4];
#pragma unroll
    for (int o = 16; o > 0; o >>= 1) s += __shfl_xor_sync(0xffffffffu, s, o);
    if ((tid & 31) == 0) red1[tid >> 5] = s;
    __syncthreads();
    float mu = (red1[0] + red1[1] + red1[2] + red1[3]) * (1.f / (float)DD);

    float q = 0.f;
#pragma unroll
    for (int i = 0; i < 4; i++) {
        float d = v[i] - mu;
        q += d * d;
    }
#pragma unroll
    for (int o = 16; o > 0; o >>= 1) q += __shfl_xor_sync(0xffffffffu, q, o);
    if ((tid & 31) == 0) red2[tid >> 5] = q;
    __syncthreads();
    float var = (red2[0] + red2[1] + red2[2] + red2[3]) * (1.f / (float)DD);
    float rstd = rsqrtf(var + 1e-5f);
#pragma unroll
    for (int i = 0; i < 4; i++) {
        int c = tid + i * 128;
        xr[c] = (v[i] - mu) * rstd * g[c] + be[c];
    }
}

// ---------------------------------------------------------------------------
// Small projection: out[M,N] = A[M,K] @ W[K,N] + bias  (N tiny: 5/6)
// ---------------------------------------------------------------------------
__global__ void proj_small_kernel(const float* __restrict__ A,
                                  const float* __restrict__ W,
                                  const float* __restrict__ bias,
                                  float* __restrict__ out,
                                  int M, int N, int K)
{
    int idx = blockIdx.x * blockDim.x + threadIdx.x;
    if (idx >= M * N) return;
    int m = idx / N, n = idx - m * N;
    const float* a = A + (size_t)m * K;
    float s = bias[n];
    for (int k = 0; k < K; k++) s += a[k] * W[(size_t)k * N + n];
    out[idx] = s;
}

// ---------------------------------------------------------------------------
// Host launcher
// ---------------------------------------------------------------------------
extern "C" void kernel_launch(void* const* d_in, const int* in_sizes, int n_in,
                              void* d_out, int out_size)
{
    const float* z_style   = (const float*)d_in[0];
    const float* z_skill   = (const float*)d_in[1];
    const float* W_lat     = (const float*)d_in[2];
    const float* b_lat     = (const float*)d_in[3];
    const float* temp_bias = (const float*)d_in[4];
    const float* Wq  = (const float*)d_in[5];
    const float* bq  = (const float*)d_in[6];
    const float* Wk  = (const float*)d_in[7];
    const float* bk  = (const float*)d_in[8];
    const float* Wv  = (const float*)d_in[9];
    const float* bv  = (const float*)d_in[10];
    const float* Wo  = (const float*)d_in[11];
    const float* bo  = (const float*)d_in[12];
    const float* g1  = (const float*)d_in[13];
    const float* be1 = (const float*)d_in[14];
    const float* g2  = (const float*)d_in[15];
    const float* be2 = (const float*)d_in[16];
    const float* W1  = (const float*)d_in[17];
    const float* bf1 = (const float*)d_in[18];
    const float* W2  = (const float*)d_in[19];
    const float* bf2 = (const float*)d_in[20];
    const float* Wp1 = (const float*)d_in[21];
    const float* bp1 = (const float*)d_in[22];
    const float* Wp2 = (const float*)d_in[23];
    const float* bp2 = (const float*)d_in[24];
    const float* Ws1 = (const float*)d_in[25];
    const float* bs1 = (const float*)d_in[26];
    const float* Ws2 = (const float*)d_in[27];
    const float* bs2 = (const float*)d_in[28];
    float* out = (float*)d_out;

    float *x, *q, *k, *v, *ctx, *tmp, *h1, *t1, *z, *s1;
    cudaGetSymbolAddress((void**)&x,   g_x);
    cudaGetSymbolAddress((void**)&q,   g_q);
    cudaGetSymbolAddress((void**)&k,   g_k);
    cudaGetSymbolAddress((void**)&v,   g_v);
    cudaGetSymbolAddress((void**)&ctx, g_ctx);
    cudaGetSymbolAddress((void**)&tmp, g_tmp);
    cudaGetSymbolAddress((void**)&h1,  g_h1);
    cudaGetSymbolAddress((void**)&t1,  g_t1);
    cudaGetSymbolAddress((void**)&z,   g_z);
    cudaGetSymbolAddress((void**)&s1,  g_s1);

    // z = concat(z_style, z_skill)
    concat_z_kernel<<<(BB * LAT + 255) / 256, 256>>>(z_style, z_skill, z);

    // x = gelu(z @ W_lat + b_lat)   [128, 102400] -> viewed as [B,S,D]
    sgemm_kernel<1><<<dim3((DD * SS) / 128, BB / 128), 256>>>(
        BB, DD * SS, LAT, z, W_lat, b_lat, x);

    // x += positional encoding
    add_pe_kernel<<<(NTOK * DD + 255) / 256, 256>>>(x);

    for (int l = 0; l < LL; l++) {
        const float* wq = Wq + (size_t)l * DD * DD;
        const float* wk = Wk + (size_t)l * DD * DD;
        const float* wv = Wv + (size_t)l * DD * DD;
        const float* wo = Wo + (size_t)l * DD * DD;
        const float* w1 = W1 + (size_t)l * DD * DFF;
        const float* w2 = W2 + (size_t)l * DFF * DD;

        dim3 gProj(DD / 128, NTOK / 128);   // (4, 200)
        sgemm_kernel<0><<<gProj, 256>>>(NTOK, DD, DD, x, wq, bq + l * DD, q);
        sgemm_kernel<0><<<gProj, 256>>>(NTOK, DD, DD, x, wk, bk + l * DD, k);
        sgemm_kernel<0><<<gProj, 256>>>(NTOK, DD, DD, x, wv, bv + l * DD, v);

        attn_kernel<<<dim3(8, HH, BB), 256>>>(q, k, v, temp_bias, ctx);

        sgemm_kernel<0><<<gProj, 256>>>(NTOK, DD, DD, ctx, wo, bo + l * DD, tmp);
        ln_kernel<<<NTOK, 128>>>(x, tmp, g1 + l * DD, be1 + l * DD);

        sgemm_kernel<1><<<dim3(DFF / 128, NTOK / 128), 256>>>(
            NTOK, DFF, DD, x, w1, bf1 + l * DFF, h1);
        sgemm_kernel<0><<<gProj, 256>>>(NTOK, DD, DFF, h1, w2, bf2 + l * DD, tmp);
        ln_kernel<<<NTOK, 128>>>(x, tmp, g2 + l * DD, be2 + l * DD);
    }

    // trajectory head: t1 = gelu(x @ Wp1 + bp1); traj = t1 @ Wp2 + bp2
    sgemm_kernel<1><<<dim3((DD / 2) / 128, NTOK / 128), 256>>>(
        NTOK, DD / 2, DD, x, Wp1, bp1, t1);
    proj_small_kernel<<<(NTOK * OUTD + 255) / 256, 256>>>(
        t1, Wp2, bp2, out, NTOK, OUTD, DD / 2);

    // signature head: s1 = gelu(z @ Ws1 + bs1); sig = s1 @ Ws2 + bs2
    sgemm_kernel<1><<<dim3((DD / 2) / 128, BB / 128), 256>>>(
        BB, DD / 2, LAT, z, Ws1, bs1, s1);
    proj_small_kernel<<<(BB * 5 + 255) / 256, 256>>>(
        s1, Ws2, bs2, out + (size_t)NTOK * OUTD, BB, 5, DD / 2);
}

// round 3
// speedup vs baseline: 2.7641x; 2.7641x over previous
#include <cuda_runtime.h>
#include <cuda_fp16.h>
#include <cstdint>
#include <cstddef>

// ---------------------------------------------------------------------------
// Problem constants
// ---------------------------------------------------------------------------
#define BB   128
#define DD   512
#define HH   8
#define LL   6
#define SS   200
#define LAT  256
#define OUTD 6
#define DKH  64
#define DFF  2048
#define NTOK (BB*SS)   // 25600

// ---------------------------------------------------------------------------
// Device scratch (allocation-free rule: __device__ globals)
// ---------------------------------------------------------------------------
__device__ __align__(256) float  g_x   [NTOK*DD];
__device__ __align__(256) float  g_tmp [NTOK*DD];
__device__ __align__(256) float  g_t1  [NTOK*(DD/2)];
__device__ __align__(256) float  g_s1  [BB*(DD/2)];
__device__ __align__(256) float  g_bqkv[LL*3*DD];

__device__ __align__(256) __half g_z16  [BB*LAT];
__device__ __align__(256) __half g_x16  [NTOK*DD];
__device__ __align__(256) __half g_qkv16[NTOK*3*DD];
__device__ __align__(256) __half g_ctx16[NTOK*DD];
__device__ __align__(256) __half g_h116 [NTOK*DFF];

// fp16 transposed weights [N][K]
__device__ __align__(256) __half g_wqkvT[LL*3*DD*DD];
__device__ __align__(256) __half g_woT  [LL*DD*DD];
__device__ __align__(256) __half g_w1T  [LL*DFF*DD];
__device__ __align__(256) __half g_w2T  [LL*DD*DFF];
__device__ __align__(256) __half g_wlatT[(size_t)(DD*SS)*LAT];
__device__ __align__(256) __half g_wp1T [(DD/2)*DD];
__device__ __align__(256) __half g_ws1T [(DD/2)*LAT];

// ---------------------------------------------------------------------------
// Helpers
// ---------------------------------------------------------------------------
__device__ __forceinline__ uint32_t smem_u32(const void* p) {
    uint32_t a;
    asm("{ .reg .u64 t; cvta.to.shared.u64 t, %1; cvt.u32.u64 %0, t; }"
        : "=r"(a) : "l"(p));
    return a;
}
__device__ __forceinline__ float gelu_f(float x) {
    return 0.5f * x * (1.0f + erff(x * 0.7071067811865475f));
}

#define LDMATRIX_X4(r0, r1, r2, r3, addr)                                     \
    asm volatile("ldmatrix.sync.aligned.m8n8.x4.shared.b16 "                  \
                 "{%0, %1, %2, %3}, [%4];"                                    \
                 : "=r"(r0), "=r"(r1), "=r"(r2), "=r"(r3) : "r"(addr))

#define MMA16816(c, a, b)                                                     \
    asm volatile("mma.sync.aligned.m16n8k16.row.col.f32.f16.f16.f32 "         \
                 "{%0, %1, %2, %3}, {%4, %5, %6, %7}, {%8, %9}, "             \
                 "{%0, %1, %2, %3};"                                          \
                 : "+f"((c)[0]), "+f"((c)[1]), "+f"((c)[2]), "+f"((c)[3])     \
                 : "r"((a)[0]), "r"((a)[1]), "r"((a)[2]), "r"((a)[3]),        \
                   "r"((b)[0]), "r"((b)[1]))

// ---------------------------------------------------------------------------
// fp16 tensor-core GEMM (mma.sync):  C[M,N] = act(A[M,K] @ Bt[N,K]^T + bias)
//   A fp16 row-major [M,K], Bt fp16 row-major [N,K]
//   M%128==0, N%128==0, K%64==0, K>=128.
//   grid = (N/128, M/128), block = 256 (8 warps, 2x4 warp grid, 64x32/warp).
//   OM bit0: write fp32 C; bit1: write fp16 C16.
// ---------------------------------------------------------------------------
#define SROW 72                       // padded row stride in halves (144 B)
#define ATILE (128*SROW*2)            // 18432 B per buffer
#define GSMEM (4*ATILE)               // A0 A1 B0 B1

template <int ACT, int OM>
__global__ void __launch_bounds__(256)
hgemm_kernel(int M, int N, int K,
             const __half* __restrict__ A, const __half* __restrict__ Bt,
             const float* __restrict__ bias,
             float* __restrict__ C, __half* __restrict__ C16)
{
    extern __shared__ char smem[];
    const uint32_t sb = smem_u32(smem);
    const int tid  = threadIdx.x;
    const int wid  = tid >> 5;
    const int lane = tid & 31;
    const int wm   = wid >> 2;        // 0..1
    const int wn   = wid & 3;         // 0..3

    const size_t n0 = (size_t)blockIdx.x * 128;
    const size_t m0 = (size_t)blockIdx.y * 128;
    const __half* Ab = A  + m0 * (size_t)K;
    const __half* Bb = Bt + n0 * (size_t)K;
    const int NS = K >> 6;

    // per-thread global->smem mapping: 4 iters, 16B each, rows of 64 halves
    const int ldr = tid >> 3;          // row 0..31 (+32 per iter)
    const int ldc = (tid & 7) << 3;    // halves 0..56

    auto load_stage = [&](int s) {
        const uint32_t buf = (uint32_t)(s & 1);
        const uint32_t sa  = sb + buf * ATILE;
        const uint32_t sbb = sb + 2 * ATILE + buf * ATILE;
        const int k0 = s << 6;
#pragma unroll
        for (int i = 0; i < 4; i++) {
            int r = ldr + (i << 5);
            uint32_t off = (uint32_t)(r * (SROW * 2) + ldc * 2);
            const void* ag = Ab + (size_t)r * K + k0 + ldc;
            asm volatile("cp.async.cg.shared.global [%0], [%1], 16;"
                         :: "r"(sa + off), "l"(ag) : "memory");
            const void* bg = Bb + (size_t)r * K + k0 + ldc;
            asm volatile("cp.async.cg.shared.global [%0], [%1], 16;"
                         :: "r"(sbb + off), "l"(bg) : "memory");
        }
        asm volatile("cp.async.commit_group;" ::: "memory");
    };

    load_stage(0);
    load_stage(1);

    float acc[4][4][4];
#pragma unroll
    for (int i = 0; i < 4; i++)
#pragma unroll
        for (int j = 0; j < 4; j++)
#pragma unroll
            for (int kq = 0; kq < 4; kq++) acc[i][j][kq] = 0.f;

    // ldmatrix per-lane row/col-offset (in halves) within a k16 step
    const int a_row = wm * 64 + (lane & 15);         // + mt*16
    const int a_kof = (lane >> 4) << 3;
    const int b_row = wn * 32 + (lane & 7) + ((lane >> 4) << 3);  // + nt2*16
    const int b_kof = ((lane >> 3) & 1) << 3;

    for (int s = 0; s < NS; s++) {
        if (s + 1 < NS) asm volatile("cp.async.wait_group 1;" ::: "memory");
        else            asm volatile("cp.async.wait_group 0;" ::: "memory");
        __syncthreads();

        const uint32_t buf = (uint32_t)(s & 1);
        const uint32_t sa  = sb + buf * ATILE;
        const uint32_t sbb = sb + 2 * ATILE + buf * ATILE;

#pragma unroll
        for (int ks = 0; ks < 4; ks++) {
            uint32_t af[4][4];
#pragma unroll
            for (int mt = 0; mt < 4; mt++) {
                uint32_t addr = sa +
                    (uint32_t)((a_row + mt * 16) * (SROW * 2) +
                               (ks * 16 + a_kof) * 2);
                LDMATRIX_X4(af[mt][0], af[mt][1], af[mt][2], af[mt][3], addr);
            }
            uint32_t bf[4][2];
#pragma unroll
            for (int nt2 = 0; nt2 < 2; nt2++) {
                uint32_t addr = sbb +
                    (uint32_t)((b_row + nt2 * 16) * (SROW * 2) +
                               (ks * 16 + b_kof) * 2);
                LDMATRIX_X4(bf[2*nt2][0], bf[2*nt2][1],
                            bf[2*nt2+1][0], bf[2*nt2+1][1], addr);
            }
#pragma unroll
            for (int mt = 0; mt < 4; mt++)
#pragma unroll
                for (int nt = 0; nt < 4; nt++)
                    MMA16816(acc[mt][nt], af[mt], bf[nt]);
        }
        if (s + 2 < NS) {
            __syncthreads();
            load_stage(s + 2);
        }
    }

    // --- epilogue ---
#pragma unroll
    for (int mt = 0; mt < 4; mt++) {
#pragma unroll
        for (int nt = 0; nt < 4; nt++) {
            const size_t col = n0 + wn * 32 + nt * 8 + (lane & 3) * 2;
            const float b0 = bias[col], b1 = bias[col + 1];
#pragma unroll
            for (int hh = 0; hh < 2; hh++) {
                const size_t row = m0 + wm * 64 + mt * 16 + (lane >> 2) + hh * 8;
                float v0 = acc[mt][nt][2*hh]   + b0;
                float v1 = acc[mt][nt][2*hh+1] + b1;
                if (ACT == 1) { v0 = gelu_f(v0); v1 = gelu_f(v1); }
                if (OM & 1) {
                    float2* dst = (float2*)(C + row * (size_t)N + col);
                    *dst = make_float2(v0, v1);
                }
                if (OM & 2) {
                    __half2* dst = (__half2*)(C16 + row * (size_t)N + col);
                    *dst = __floats2half2_rn(v0, v1);
                }
            }
        }
    }
}

// ---------------------------------------------------------------------------
// transpose + convert: src f32 [R,C] -> dst f16 [C,R]  (R,C % 32 == 0)
// ---------------------------------------------------------------------------
__global__ void transp_kernel(const float* __restrict__ src,
                              __half* __restrict__ dst,
                              int R, int C, size_t sstride, size_t dstride)
{
    __shared__ float t[32][33];
    src += (size_t)blockIdx.z * sstride;
    dst += (size_t)blockIdx.z * dstride;
    const int c0 = blockIdx.x << 5, r0 = blockIdx.y << 5;
    const int x = threadIdx.x, y = threadIdx.y;
#pragma unroll
    for (int j = 0; j < 32; j += 8)
        t[y + j][x] = src[(size_t)(r0 + y + j) * C + c0 + x];
    __syncthreads();
#pragma unroll
    for (int j = 0; j < 32; j += 8)
        dst[(size_t)(c0 + y + j) * R + r0 + x] = __float2half(t[x][y + j]);
}

__global__ void concat_z_kernel(const float* __restrict__ zs,
                                const float* __restrict__ zk,
                                __half* __restrict__ z16)
{
    int i = blockIdx.x * blockDim.x + threadIdx.x;
    if (i >= BB * LAT) return;
    int b = i >> 8, c = i & 255;
    float v = (c < 128) ? zs[b * 128 + c] : zk[b * 128 + (c - 128)];
    z16[i] = __float2half(v);
}

__global__ void concat_bqkv_kernel(const float* __restrict__ bq,
                                   const float* __restrict__ bk,
                                   const float* __restrict__ bv,
                                   float* __restrict__ dst)
{
    int i = blockIdx.x * blockDim.x + threadIdx.x;
    if (i >= LL * 3 * DD) return;
    int l = i / (3 * DD), r = i % (3 * DD), part = r / DD, c = r % DD;
    const float* s = (part == 0) ? bq : (part == 1) ? bk : bv;
    dst[i] = s[l * DD + c];
}

__global__ void add_pe_kernel(float* __restrict__ x, __half* __restrict__ x16)
{
    int idx = blockIdx.x * blockDim.x + threadIdx.x;
    if (idx >= NTOK * DD) return;
    int d = idx & (DD - 1);
    int s = (idx >> 9) % SS;
    const float c = -9.210340371976184f / (float)DD;
    int de = d & ~1;
    float div = expf((float)de * c);
    float ang = (float)s * div;
    float v = x[idx] + ((d & 1) ? cosf(ang) : sinf(ang));
    x[idx] = v;
    x16[idx] = __float2half(v);
}

// ---------------------------------------------------------------------------
// Fused attention, fp16 QKV in (packed [tok][1536]), fp16 ctx out.
// grid = (8, H, B), block = 256.
// ---------------------------------------------------------------------------
__global__ __launch_bounds__(256) void attn_kernel(
    const __half* __restrict__ QKV, const float* __restrict__ bias,
    __half* __restrict__ O)
{
    __shared__ float q_sm[25][65];
    __shared__ float kv_sm[50][65];
    __shared__ float sc[25][200];

    const int it  = blockIdx.x;
    const int h   = blockIdx.y;
    const int b   = blockIdx.z;
    const int tid = threadIdx.x;
    const int i0  = it * 25;
    const size_t tok0 = (size_t)b * SS;
    const int hoff = h * DKH;

    for (int p = tid; p < 25 * 64; p += 256) {
        int i = p >> 6, d = p & 63;
        q_sm[i][d] = __half2float(QKV[(tok0 + i0 + i) * 1536 + hoff + d]);
    }

    for (int jt = 0; jt < 4; jt++) {
        int j0 = jt * 50;
        __syncthreads();
        for (int p = tid; p < 50 * 64; p += 256) {
            int j = p >> 6, d = p & 63;
            kv_sm[j][d] = __half2float(QKV[(tok0 + j0 + j) * 1536 + 512 + hoff + d]);
        }
        __syncthreads();
        for (int p = tid; p < 25 * 50; p += 256) {
            int i = p / 50, j = p - i * 50;
            float s = 0.f;
#pragma unroll 16
            for (int d = 0; d < 64; d++) s += q_sm[i][d] * kv_sm[j][d];
            sc[i][j0 + j] = s * 0.125f +
                bias[((size_t)h * SS + (i0 + i)) * SS + (j0 + j)];
        }
    }
    __syncthreads();

    const int wid = tid >> 5, lane = tid & 31;
    for (int i = wid; i < 25; i += 8) {
        float m = -1e30f;
        for (int j = lane; j < SS; j += 32) m = fmaxf(m, sc[i][j]);
#pragma unroll
        for (int o = 16; o > 0; o >>= 1)
            m = fmaxf(m, __shfl_xor_sync(0xffffffffu, m, o));
        float sum = 0.f;
        for (int j = lane; j < SS; j += 32) {
            float e = expf(sc[i][j] - m);
            sc[i][j] = e;
            sum += e;
        }
#pragma unroll
        for (int o = 16; o > 0; o >>= 1)
            sum += __shfl_xor_sync(0xffffffffu, sum, o);
        float inv = 1.f / sum;
        for (int j = lane; j < SS; j += 32) sc[i][j] *= inv;
    }

    float acc[7] = {0.f, 0.f, 0.f, 0.f, 0.f, 0.f, 0.f};
    for (int jt = 0; jt < 4; jt++) {
        int j0 = jt * 50;
        __syncthreads();
        for (int p = tid; p < 50 * 64; p += 256) {
            int j = p >> 6, d = p & 63;
            kv_sm[j][d] = __half2float(QKV[(tok0 + j0 + j) * 1536 + 1024 + hoff + d]);
        }
        __syncthreads();
#pragma unroll
        for (int r = 0; r < 7; r++) {
            int p = tid + r * 256;
            if (p < 25 * 64) {
                int i = p >> 6, d = p & 63;
                float a = acc[r];
#pragma unroll 10
                for (int jj = 0; jj < 50; jj++)
                    a += sc[i][j0 + jj] * kv_sm[jj][d];
                acc[r] = a;
            }
        }
    }
#pragma unroll
    for (int r = 0; r < 7; r++) {
        int p = tid + r * 256;
        if (p < 25 * 64) {
            int i = p >> 6, d = p & 63;
            O[(tok0 + i0 + i) * DD + hoff + d] = __float2half(acc[r]);
        }
    }
}

// ---------------------------------------------------------------------------
// x = LN(x + res) * g + be, in place; also emit fp16 copy. One block per row.
// ---------------------------------------------------------------------------
__global__ __launch_bounds__(128) void ln_kernel(
    float* __restrict__ x, const float* __restrict__ res,
    const float* __restrict__ g, const float* __restrict__ be,
    __half* __restrict__ x16)
{
    const int row = blockIdx.x;
    float* xr = x + (size_t)row * DD;
    const float* rr = res + (size_t)row * DD;
    __half* hr = x16 + (size_t)row * DD;
    const int tid = threadIdx.x;

    float v[4];
    float s = 0.f;
#pragma unroll
    for (int i = 0; i < 4; i++) {
        int c = tid + i * 128;
        v[i] = xr[c] + rr[c];
        s += v[i];
    }
    __shared__ float red1[4];
    __shared__ float red2[4];
#pragma unroll
    for (int o = 16; o > 0; o >>= 1) s += __shfl_xor_sync(0xffffffffu, s, o);
    if ((tid & 31) == 0) red1[tid >> 5] = s;
    __syncthreads();
    float mu = (red1[0] + red1[1] + red1[2] + red1[3]) * (1.f / (float)DD);

    float q = 0.f;
#pragma unroll
    for (int i = 0; i < 4; i++) {
        float d = v[i] - mu;
        q += d * d;
    }
#pragma unroll
    for (int o = 16; o > 0; o >>= 1) q += __shfl_xor_sync(0xffffffffu, q, o);
    if ((tid & 31) == 0) red2[tid >> 5] = q;
    __syncthreads();
    float var = (red2[0] + red2[1] + red2[2] + red2[3]) * (1.f / (float)DD);
    float rstd = rsqrtf(var + 1e-5f);
#pragma unroll
    for (int i = 0; i < 4; i++) {
        int c = tid + i * 128;
        float o = (v[i] - mu) * rstd * g[c] + be[c];
        xr[c] = o;
        hr[c] = __float2half(o);
    }
}

__global__ void proj_small_kernel(const float* __restrict__ A,
                                  const float* __restrict__ W,
                                  const float* __restrict__ bias,
                                  float* __restrict__ out,
                                  int M, int N, int K)
{
    int idx = blockIdx.x * blockDim.x + threadIdx.x;
    if (idx >= M * N) return;
    int m = idx / N, n = idx - m * N;
    const float* a = A + (size_t)m * K;
    float s = bias[n];
    for (int k = 0; k < K; k++) s += a[k] * W[(size_t)k * N + n];
    out[idx] = s;
}

// ---------------------------------------------------------------------------
// Host launcher
// ---------------------------------------------------------------------------
extern "C" void kernel_launch(void* const* d_in, const int* in_sizes, int n_in,
                              void* d_out, int out_size)
{
    const float* z_style   = (const float*)d_in[0];
    const float* z_skill   = (const float*)d_in[1];
    const float* W_lat     = (const float*)d_in[2];
    const float* b_lat     = (const float*)d_in[3];
    const float* temp_bias = (const float*)d_in[4];
    const float* Wq  = (const float*)d_in[5];
    const float* bq  = (const float*)d_in[6];
    const float* Wk  = (const float*)d_in[7];
    const float* bk  = (const float*)d_in[8];
    const float* Wv  = (const float*)d_in[9];
    const float* bv  = (const float*)d_in[10];
    const float* Wo  = (const float*)d_in[11];
    const float* bo  = (const float*)d_in[12];
    const float* g1  = (const float*)d_in[13];
    const float* be1 = (const float*)d_in[14];
    const float* g2  = (const float*)d_in[15];
    const float* be2 = (const float*)d_in[16];
    const float* W1  = (const float*)d_in[17];
    const float* bf1 = (const float*)d_in[18];
    const float* W2  = (const float*)d_in[19];
    const float* bf2 = (const float*)d_in[20];
    const float* Wp1 = (const float*)d_in[21];
    const float* bp1 = (const float*)d_in[22];
    const float* Wp2 = (const float*)d_in[23];
    const float* bp2 = (const float*)d_in[24];
    const float* Ws1 = (const float*)d_in[25];
    const float* bs1 = (const float*)d_in[26];
    const float* Ws2 = (const float*)d_in[27];
    const float* bs2 = (const float*)d_in[28];
    float* out = (float*)d_out;

    float *x, *tmp, *t1, *s1, *bqkv;
    __half *z16, *x16, *qkv16, *ctx16, *h116;
    __half *wqkvT, *woT, *w1T, *w2T, *wlatT, *wp1T, *ws1T;
    cudaGetSymbolAddress((void**)&x,     g_x);
    cudaGetSymbolAddress((void**)&tmp,   g_tmp);
    cudaGetSymbolAddress((void**)&t1,    g_t1);
    cudaGetSymbolAddress((void**)&s1,    g_s1);
    cudaGetSymbolAddress((void**)&bqkv,  g_bqkv);
    cudaGetSymbolAddress((void**)&z16,   g_z16);
    cudaGetSymbolAddress((void**)&x16,   g_x16);
    cudaGetSymbolAddress((void**)&qkv16, g_qkv16);
    cudaGetSymbolAddress((void**)&ctx16, g_ctx16);
    cudaGetSymbolAddress((void**)&h116,  g_h116);
    cudaGetSymbolAddress((void**)&wqkvT, g_wqkvT);
    cudaGetSymbolAddress((void**)&woT,   g_woT);
    cudaGetSymbolAddress((void**)&w1T,   g_w1T);
    cudaGetSymbolAddress((void**)&w2T,   g_w2T);
    cudaGetSymbolAddress((void**)&wlatT, g_wlatT);
    cudaGetSymbolAddress((void**)&wp1T,  g_wp1T);
    cudaGetSymbolAddress((void**)&ws1T,  g_ws1T);

    cudaFuncSetAttribute(hgemm_kernel<0,1>, cudaFuncAttributeMaxDynamicSharedMemorySize, GSMEM);
    cudaFuncSetAttribute(hgemm_kernel<0,2>, cudaFuncAttributeMaxDynamicSharedMemorySize, GSMEM);
    cudaFuncSetAttribute(hgemm_kernel<1,1>, cudaFuncAttributeMaxDynamicSharedMemorySize, GSMEM);
    cudaFuncSetAttribute(hgemm_kernel<1,2>, cudaFuncAttributeMaxDynamicSharedMemorySize, GSMEM);

    const dim3 tb(32, 8);
    transp_kernel<<<dim3(16, 16, LL), tb>>>(Wq, wqkvT,                   DD, DD, (size_t)DD*DD, (size_t)3*DD*DD);
    transp_kernel<<<dim3(16, 16, LL), tb>>>(Wk, wqkvT + (size_t)DD*DD,   DD, DD, (size_t)DD*DD, (size_t)3*DD*DD);
    transp_kernel<<<dim3(16, 16, LL), tb>>>(Wv, wqkvT + (size_t)2*DD*DD, DD, DD, (size_t)DD*DD, (size_t)3*DD*DD);
    transp_kernel<<<dim3(16, 16, LL), tb>>>(Wo, woT,  DD, DD,  (size_t)DD*DD,  (size_t)DD*DD);
    transp_kernel<<<dim3(64, 16, LL), tb>>>(W1, w1T,  DD, DFF, (size_t)DD*DFF, (size_t)DFF*DD);
    transp_kernel<<<dim3(16, 64, LL), tb>>>(W2, w2T,  DFF, DD, (size_t)DFF*DD, (size_t)DD*DFF);
    transp_kernel<<<dim3((DD*SS)/32, LAT/32, 1), tb>>>(W_lat, wlatT, LAT, DD*SS, 0, 0);
    transp_kernel<<<dim3((DD/2)/32, DD/32, 1),  tb>>>(Wp1, wp1T, DD, DD/2, 0, 0);
    transp_kernel<<<dim3((DD/2)/32, LAT/32, 1), tb>>>(Ws1, ws1T, LAT, DD/2, 0, 0);

    concat_z_kernel<<<(BB * LAT + 255) / 256, 256>>>(z_style, z_skill, z16);
    concat_bqkv_kernel<<<(LL * 3 * DD + 255) / 256, 256>>>(bq, bk, bv, bqkv);

    // x = gelu(z @ W_lat + b_lat)  [128, 102400]
    hgemm_kernel<1,1><<<dim3((DD*SS)/128, 1), 256, GSMEM>>>(
        BB, DD*SS, LAT, z16, wlatT, b_lat, x, nullptr);
    add_pe_kernel<<<(NTOK * DD + 255) / 256, 256>>>(x, x16);

    for (int l = 0; l < LL; l++) {
        const __half* wqkv_l = wqkvT + (size_t)l * 3 * DD * DD;
        const __half* wo_l   = woT   + (size_t)l * DD * DD;
        const __half* w1_l   = w1T   + (size_t)l * DFF * DD;
        const __half* w2_l   = w2T   + (size_t)l * DD * DFF;

        hgemm_kernel<0,2><<<dim3(12, NTOK/128), 256, GSMEM>>>(
            NTOK, 3*DD, DD, x16, wqkv_l, bqkv + (size_t)l*3*DD, nullptr, qkv16);

        attn_kernel<<<dim3(8, HH, BB), 256>>>(qkv16, temp_bias, ctx16);

        hgemm_kernel<0,1><<<dim3(4, NTOK/128), 256, GSMEM>>>(
            NTOK, DD, DD, ctx16, wo_l, bo + (size_t)l*DD, tmp, nullptr);
        ln_kernel<<<NTOK, 128>>>(x, tmp, g1 + l*DD, be1 + l*DD, x16);

        hgemm_kernel<1,2><<<dim3(16, NTOK/128), 256, GSMEM>>>(
            NTOK, DFF, DD, x16, w1_l, bf1 + (size_t)l*DFF, nullptr, h116);
        hgemm_kernel<0,1><<<dim3(4, NTOK/128), 256, GSMEM>>>(
            NTOK, DD, DFF, h116, w2_l, bf2 + (size_t)l*DD, tmp, nullptr);
        ln_kernel<<<NTOK, 128>>>(x, tmp, g2 + l*DD, be2 + l*DD, x16);
    }

    hgemm_kernel<1,1><<<dim3((DD/2)/128, NTOK/128), 256, GSMEM>>>(
        NTOK, DD/2, DD, x16, wp1T, bp1, t1, nullptr);
    proj_small_kernel<<<(NTOK * OUTD + 255) / 256, 256>>>(
        t1, Wp2, bp2, out, NTOK, OUTD, DD/2);

    hgemm_kernel<1,1><<<dim3((DD/2)/128, 1), 256, GSMEM>>>(
        BB, DD/2, LAT, z16, ws1T, bs1, s1, nullptr);
    proj_small_kernel<<<(BB * 5 + 255) / 256, 256>>>(
        s1, Ws2, bs2, out + (size_t)NTOK * OUTD, BB, 5, DD/2);
}

// round 4
// speedup vs baseline: 5.7786x; 2.0906x over previous
#include <cuda_runtime.h>
#include <cuda_fp16.h>
#include <cstdint>
#include <cstddef>

// ---------------------------------------------------------------------------
// Problem constants
// ---------------------------------------------------------------------------
#define BB   128
#define DD   512
#define HH   8
#define LL   6
#define SS   200
#define LAT  256
#define OUTD 6
#define DKH  64
#define DFF  2048
#define NTOK (BB*SS)   // 25600

// ---------------------------------------------------------------------------
// Device scratch
// ---------------------------------------------------------------------------
__device__ __align__(256) float  g_x   [NTOK*DD];
__device__ __align__(256) float  g_tmp [NTOK*DD];
__device__ __align__(256) float  g_t1  [NTOK*(DD/2)];
__device__ __align__(256) float  g_s1  [BB*(DD/2)];
__device__ __align__(256) float  g_bqkv[LL*3*DD];

__device__ __align__(256) __half g_z16  [BB*LAT];
__device__ __align__(256) __half g_x16  [NTOK*DD];
__device__ __align__(256) __half g_qkv16[NTOK*3*DD];
__device__ __align__(256) __half g_ctx16[NTOK*DD];
__device__ __align__(256) __half g_h116 [NTOK*DFF];

__device__ __align__(256) __half g_wqkvT[LL*3*DD*DD];
__device__ __align__(256) __half g_woT  [LL*DD*DD];
__device__ __align__(256) __half g_w1T  [LL*DFF*DD];
__device__ __align__(256) __half g_w2T  [LL*DD*DFF];
__device__ __align__(256) __half g_wlatT[(size_t)(DD*SS)*LAT];
__device__ __align__(256) __half g_wp1T [(DD/2)*DD];
__device__ __align__(256) __half g_ws1T [(DD/2)*LAT];

// ---------------------------------------------------------------------------
// Helpers
// ---------------------------------------------------------------------------
__device__ __forceinline__ uint32_t smem_u32(const void* p) {
    uint32_t a;
    asm("{ .reg .u64 t; cvta.to.shared.u64 t, %1; cvt.u32.u64 %0, t; }"
        : "=r"(a) : "l"(p));
    return a;
}
__device__ __forceinline__ float gelu_f(float x) {
    return 0.5f * x * (1.0f + erff(x * 0.7071067811865475f));
}

#define LDMATRIX_X4(r0, r1, r2, r3, addr)                                     \
    asm volatile("ldmatrix.sync.aligned.m8n8.x4.shared.b16 "                  \
                 "{%0, %1, %2, %3}, [%4];"                                    \
                 : "=r"(r0), "=r"(r1), "=r"(r2), "=r"(r3) : "r"(addr))

#define LDMATRIX_X4_T(r0, r1, r2, r3, addr)                                   \
    asm volatile("ldmatrix.sync.aligned.m8n8.x4.trans.shared.b16 "            \
                 "{%0, %1, %2, %3}, [%4];"                                    \
                 : "=r"(r0), "=r"(r1), "=r"(r2), "=r"(r3) : "r"(addr))

#define MMA16816(c, a, b)                                                     \
    asm volatile("mma.sync.aligned.m16n8k16.row.col.f32.f16.f16.f32 "         \
                 "{%0, %1, %2, %3}, {%4, %5, %6, %7}, {%8, %9}, "             \
                 "{%0, %1, %2, %3};"                                          \
                 : "+f"((c)[0]), "+f"((c)[1]), "+f"((c)[2]), "+f"((c)[3])     \
                 : "r"((a)[0]), "r"((a)[1]), "r"((a)[2]), "r"((a)[3]),        \
                   "r"((b)[0]), "r"((b)[1]))

// ---------------------------------------------------------------------------
// fp16 tensor-core GEMM (mma.sync):  C[M,N] = act(A[M,K] @ Bt[N,K]^T + bias)
// ---------------------------------------------------------------------------
#define SROW 72
#define ATILE (128*SROW*2)
#define GSMEM (4*ATILE)

template <int ACT, int OM>
__global__ void __launch_bounds__(256)
hgemm_kernel(int M, int N, int K,
             const __half* __restrict__ A, const __half* __restrict__ Bt,
             const float* __restrict__ bias,
             float* __restrict__ C, __half* __restrict__ C16)
{
    extern __shared__ char smem[];
    const uint32_t sb = smem_u32(smem);
    const int tid  = threadIdx.x;
    const int wid  = tid >> 5;
    const int lane = tid & 31;
    const int wm   = wid >> 2;
    const int wn   = wid & 3;

    const size_t n0 = (size_t)blockIdx.x * 128;
    const size_t m0 = (size_t)blockIdx.y * 128;
    const __half* Ab = A  + m0 * (size_t)K;
    const __half* Bb = Bt + n0 * (size_t)K;
    const int NS = K >> 6;

    const int ldr = tid >> 3;
    const int ldc = (tid & 7) << 3;

    auto load_stage = [&](int s) {
        const uint32_t buf = (uint32_t)(s & 1);
        const uint32_t sa  = sb + buf * ATILE;
        const uint32_t sbb = sb + 2 * ATILE + buf * ATILE;
        const int k0 = s << 6;
#pragma unroll
        for (int i = 0; i < 4; i++) {
            int r = ldr + (i << 5);
            uint32_t off = (uint32_t)(r * (SROW * 2) + ldc * 2);
            const void* ag = Ab + (size_t)r * K + k0 + ldc;
            asm volatile("cp.async.cg.shared.global [%0], [%1], 16;"
                         :: "r"(sa + off), "l"(ag) : "memory");
            const void* bg = Bb + (size_t)r * K + k0 + ldc;
            asm volatile("cp.async.cg.shared.global [%0], [%1], 16;"
                         :: "r"(sbb + off), "l"(bg) : "memory");
        }
        asm volatile("cp.async.commit_group;" ::: "memory");
    };

    load_stage(0);
    load_stage(1);

    float acc[4][4][4];
#pragma unroll
    for (int i = 0; i < 4; i++)
#pragma unroll
        for (int j = 0; j < 4; j++)
#pragma unroll
            for (int kq = 0; kq < 4; kq++) acc[i][j][kq] = 0.f;

    const int a_row = wm * 64 + (lane & 15);
    const int a_kof = (lane >> 4) << 3;
    const int b_row = wn * 32 + (lane & 7) + ((lane >> 4) << 3);
    const int b_kof = ((lane >> 3) & 1) << 3;

    for (int s = 0; s < NS; s++) {
        if (s + 1 < NS) asm volatile("cp.async.wait_group 1;" ::: "memory");
        else            asm volatile("cp.async.wait_group 0;" ::: "memory");
        __syncthreads();

        const uint32_t buf = (uint32_t)(s & 1);
        const uint32_t sa  = sb + buf * ATILE;
        const uint32_t sbb = sb + 2 * ATILE + buf * ATILE;

#pragma unroll
        for (int ks = 0; ks < 4; ks++) {
            uint32_t af[4][4];
#pragma unroll
            for (int mt = 0; mt < 4; mt++) {
                uint32_t addr = sa +
                    (uint32_t)((a_row + mt * 16) * (SROW * 2) +
                               (ks * 16 + a_kof) * 2);
                LDMATRIX_X4(af[mt][0], af[mt][1], af[mt][2], af[mt][3], addr);
            }
            uint32_t bf[4][2];
#pragma unroll
            for (int nt2 = 0; nt2 < 2; nt2++) {
                uint32_t addr = sbb +
                    (uint32_t)((b_row + nt2 * 16) * (SROW * 2) +
                               (ks * 16 + b_kof) * 2);
                LDMATRIX_X4(bf[2*nt2][0], bf[2*nt2][1],
                            bf[2*nt2+1][0], bf[2*nt2+1][1], addr);
            }
#pragma unroll
            for (int mt = 0; mt < 4; mt++)
#pragma unroll
                for (int nt = 0; nt < 4; nt++)
                    MMA16816(acc[mt][nt], af[mt], bf[nt]);
        }
        if (s + 2 < NS) {
            __syncthreads();
            load_stage(s + 2);
        }
    }

#pragma unroll
    for (int mt = 0; mt < 4; mt++) {
#pragma unroll
        for (int nt = 0; nt < 4; nt++) {
            const size_t col = n0 + wn * 32 + nt * 8 + (lane & 3) * 2;
            const float b0 = bias[col], b1 = bias[col + 1];
#pragma unroll
            for (int hh = 0; hh < 2; hh++) {
                const size_t row = m0 + wm * 64 + mt * 16 + (lane >> 2) + hh * 8;
                float v0 = acc[mt][nt][2*hh]   + b0;
                float v1 = acc[mt][nt][2*hh+1] + b1;
                if (ACT == 1) { v0 = gelu_f(v0); v1 = gelu_f(v1); }
                if (OM & 1) {
                    float2* dst = (float2*)(C + row * (size_t)N + col);
                    *dst = make_float2(v0, v1);
                }
                if (OM & 2) {
                    __half2* dst = (__half2*)(C16 + row * (size_t)N + col);
                    *dst = __floats2half2_rn(v0, v1);
                }
            }
        }
    }
}

// ---------------------------------------------------------------------------
// Tensor-core attention. grid = (4, H, B); block = 256 (8 warps).
// Per block: 64 query rows (i0=64*it), all 200 keys (padded to 224).
// QKV packed [tok][1536]; ctx out fp16 [tok][512].
// ---------------------------------------------------------------------------
#define KVST 72                 // Q/K/V smem row stride (halves)
#define SJP  224                // padded j
#define PST  232                // P row stride (halves), 464 B = 29*16
#define AQ_OFF 0                // 64*144   = 9216
#define AK_OFF 9216             // 224*144  = 32256
#define AV_OFF 41472            // 224*144  = 32256
#define AS_OFF 73728            // 64*224*4 = 57344
#define AP_OFF 131072           // 64*464   = 29696
#define ASMEM  160768

__global__ void __launch_bounds__(256)
attn_mma_kernel(const __half* __restrict__ QKV, const float* __restrict__ bias,
                __half* __restrict__ O)
{
    extern __shared__ char smem[];
    const uint32_t sb = smem_u32(smem);
    const int it  = blockIdx.x;
    const int h   = blockIdx.y;
    const int b   = blockIdx.z;
    const int tid = threadIdx.x;
    const int wid = tid >> 5, lane = tid & 31;
    const int i0  = it * 64;
    const size_t tok0 = (size_t)b * SS;
    const int hoff = h * DKH;

    // ---- load Q (zero-fill invalid rows) ----
    for (int p = tid; p < 64 * 8; p += 256) {
        int r = p >> 3, c = (p & 7) << 3;
        uint4 val = make_uint4(0, 0, 0, 0);
        if (i0 + r < SS)
            val = *(const uint4*)(QKV + (tok0 + i0 + r) * 1536 + hoff + c);
        *(uint4*)(smem + AQ_OFF + r * (KVST * 2) + c * 2) = val;
    }
    // ---- load K, V (zero-fill j >= 200) ----
    for (int p = tid; p < SJP * 8; p += 256) {
        int j = p >> 3, c = (p & 7) << 3;
        uint4 kv = make_uint4(0, 0, 0, 0), vv = make_uint4(0, 0, 0, 0);
        if (j < SS) {
            kv = *(const uint4*)(QKV + (tok0 + j) * 1536 + 512 + hoff + c);
            vv = *(const uint4*)(QKV + (tok0 + j) * 1536 + 1024 + hoff + c);
        }
        *(uint4*)(smem + AK_OFF + j * (KVST * 2) + c * 2) = kv;
        *(uint4*)(smem + AV_OFF + j * (KVST * 2) + c * 2) = vv;
    }
    __syncthreads();

    // ---- scores = QK^T / 8 -> ss (fp32) ----
    {
        const int wm = wid & 3;            // m16 tile
        const int wn = wid >> 1 >> 1;      // 0..1 (wid>>2), cols wn*112
        const int arow = wm * 16 + (lane & 15);
        const int akof = (lane >> 4) << 3;
        const int brow = (lane & 7) + ((lane >> 4) << 3);
        const int bkof = ((lane >> 3) & 1) << 3;
        float acc[7][2][4];
#pragma unroll
        for (int g = 0; g < 7; g++)
#pragma unroll
            for (int q = 0; q < 2; q++)
#pragma unroll
                for (int r = 0; r < 4; r++) acc[g][q][r] = 0.f;

#pragma unroll
        for (int ks = 0; ks < 4; ks++) {
            uint32_t a[4];
            uint32_t aaddr = sb + AQ_OFF +
                (uint32_t)(arow * (KVST * 2) + (ks * 16 + akof) * 2);
            LDMATRIX_X4(a[0], a[1], a[2], a[3], aaddr);
#pragma unroll
            for (int g = 0; g < 7; g++) {
                int ncol = wn * 112 + g * 16;
                uint32_t baddr = sb + AK_OFF +
                    (uint32_t)((ncol + brow) * (KVST * 2) + (ks * 16 + bkof) * 2);
                uint32_t b0, b1, b2, b3;
                LDMATRIX_X4(b0, b1, b2, b3, baddr);
                uint32_t bf0[2] = {b0, b1}, bf1[2] = {b2, b3};
                MMA16816(acc[g][0], a, bf0);
                MMA16816(acc[g][1], a, bf1);
            }
        }
        float* ss = (float*)(smem + AS_OFF);
        const int r0 = wm * 16 + (lane >> 2);
#pragma unroll
        for (int g = 0; g < 7; g++)
#pragma unroll
            for (int q = 0; q < 2; q++) {
                int col = wn * 112 + g * 16 + q * 8 + (lane & 3) * 2;
                ss[r0 * SJP + col]           = acc[g][q][0] * 0.125f;
                ss[r0 * SJP + col + 1]       = acc[g][q][1] * 0.125f;
                ss[(r0 + 8) * SJP + col]     = acc[g][q][2] * 0.125f;
                ss[(r0 + 8) * SJP + col + 1] = acc[g][q][3] * 0.125f;
            }
    }
    __syncthreads();

    // ---- softmax (+bias) -> P fp16 ----
    {
        float* ss = (float*)(smem + AS_OFF);
        __half* ps = (__half*)(smem + AP_OFF);
        for (int i = wid; i < 64; i += 8) {
            int gi = i0 + i;
            if (gi < SS) {
                const float* brow = bias + ((size_t)h * SS + gi) * SS;
                float vals[7];
                float m = -1e30f;
#pragma unroll
                for (int t = 0; t < 7; t++) {
                    int j = lane + t * 32;
                    float s = -1e30f;
                    if (j < SS) s = ss[i * SJP + j] + brow[j];
                    vals[t] = s;
                    m = fmaxf(m, s);
                }
#pragma unroll
                for (int o = 16; o > 0; o >>= 1)
                    m = fmaxf(m, __shfl_xor_sync(0xffffffffu, m, o));
                float sum = 0.f;
#pragma unroll
                for (int t = 0; t < 7; t++) {
                    int j = lane + t * 32;
                    float e = (j < SS) ? expf(vals[t] - m) : 0.f;
                    vals[t] = e;
                    sum += e;
                }
#pragma unroll
                for (int o = 16; o > 0; o >>= 1)
                    sum += __shfl_xor_sync(0xffffffffu, sum, o);
                float inv = 1.f / sum;
#pragma unroll
                for (int t = 0; t < 7; t++)
                    ps[i * PST + lane + t * 32] = __float2half(vals[t] * inv);
            } else {
#pragma unroll
                for (int t = 0; t < 7; t++)
                    ps[i * PST + lane + t * 32] = __float2half(0.f);
            }
        }
    }
    __syncthreads();

    // ---- ctx = P @ V ----
    {
        const int wm = wid & 3;
        const int wn = wid >> 2;           // 0..1, cols wn*32
        const int arow = wm * 16 + (lane & 15);
        const int akof = (lane >> 4) << 3;
        const int vrow = lane & 15;
        const int vcol = (lane >> 4) << 3;
        float acc[4][4];
#pragma unroll
        for (int i = 0; i < 4; i++)
#pragma unroll
            for (int j = 0; j < 4; j++) acc[i][j] = 0.f;

#pragma unroll
        for (int ks = 0; ks < 14; ks++) {
            uint32_t a[4];
            uint32_t aaddr = sb + AP_OFF +
                (uint32_t)(arow * (PST * 2) + (ks * 16 + akof) * 2);
            LDMATRIX_X4(a[0], a[1], a[2], a[3], aaddr);
#pragma unroll
            for (int g = 0; g < 2; g++) {
                int n0c = wn * 32 + g * 16;
                uint32_t baddr = sb + AV_OFF +
                    (uint32_t)((ks * 16 + vrow) * (KVST * 2) + (n0c + vcol) * 2);
                uint32_t b0, b1, b2, b3;
                LDMATRIX_X4_T(b0, b1, b2, b3, baddr);
                uint32_t bf0[2] = {b0, b1}, bf1[2] = {b2, b3};
                MMA16816(acc[g * 2 + 0], a, bf0);
                MMA16816(acc[g * 2 + 1], a, bf1);
            }
        }
#pragma unroll
        for (int nt = 0; nt < 4; nt++) {
            int col = hoff + wn * 32 + nt * 8 + (lane & 3) * 2;
#pragma unroll
            for (int hh = 0; hh < 2; hh++) {
                int row = i0 + wm * 16 + (lane >> 2) + hh * 8;
                if (row < SS) {
                    __half2* dst = (__half2*)(O + (tok0 + row) * DD + col);
                    *dst = __floats2half2_rn(acc[nt][2 * hh], acc[nt][2 * hh + 1]);
                }
            }
        }
    }
}

// ---------------------------------------------------------------------------
// transpose + convert: src f32 [R,C] -> dst f16 [C,R]
// ---------------------------------------------------------------------------
__global__ void transp_kernel(const float* __restrict__ src,
                              __half* __restrict__ dst,
                              int R, int C, size_t sstride, size_t dstride)
{
    __shared__ float t[32][33];
    src += (size_t)blockIdx.z * sstride;
    dst += (size_t)blockIdx.z * dstride;
    const int c0 = blockIdx.x << 5, r0 = blockIdx.y << 5;
    const int x = threadIdx.x, y = threadIdx.y;
#pragma unroll
    for (int j = 0; j < 32; j += 8)
        t[y + j][x] = src[(size_t)(r0 + y + j) * C + c0 + x];
    __syncthreads();
#pragma unroll
    for (int j = 0; j < 32; j += 8)
        dst[(size_t)(c0 + y + j) * R + r0 + x] = __float2half(t[x][y + j]);
}

__global__ void concat_z_kernel(const float* __restrict__ zs,
                                const float* __restrict__ zk,
                                __half* __restrict__ z16)
{
    int i = blockIdx.x * blockDim.x + threadIdx.x;
    if (i >= BB * LAT) return;
    int b = i >> 8, c = i & 255;
    float v = (c < 128) ? zs[b * 128 + c] : zk[b * 128 + (c - 128)];
    z16[i] = __float2half(v);
}

__global__ void concat_bqkv_kernel(const float* __restrict__ bq,
                                   const float* __restrict__ bk,
                                   const float* __restrict__ bv,
                                   float* __restrict__ dst)
{
    int i = blockIdx.x * blockDim.x + threadIdx.x;
    if (i >= LL * 3 * DD) return;
    int l = i / (3 * DD), r = i % (3 * DD), part = r / DD, c = r % DD;
    const float* s = (part == 0) ? bq : (part == 1) ? bk : bv;
    dst[i] = s[l * DD + c];
}

__global__ void add_pe_kernel(float* __restrict__ x, __half* __restrict__ x16)
{
    int idx = blockIdx.x * blockDim.x + threadIdx.x;
    if (idx >= NTOK * DD) return;
    int d = idx & (DD - 1);
    int s = (idx >> 9) % SS;
    const float c = -9.210340371976184f / (float)DD;
    int de = d & ~1;
    float div = expf((float)de * c);
    float ang = (float)s * div;
    float v = x[idx] + ((d & 1) ? cosf(ang) : sinf(ang));
    x[idx] = v;
    x16[idx] = __float2half(v);
}

// ---------------------------------------------------------------------------
// x = LN(x + res) * g + be, in place; also emit fp16 copy.
// ---------------------------------------------------------------------------
__global__ void __launch_bounds__(128) ln_kernel(
    float* __restrict__ x, const float* __restrict__ res,
    const float* __restrict__ g, const float* __restrict__ be,
    __half* __restrict__ x16)
{
    const int row = blockIdx.x;
    float* xr = x + (size_t)row * DD;
    const float* rr = res + (size_t)row * DD;
    __half* hr = x16 + (size_t)row * DD;
    const int tid = threadIdx.x;

    float v[4];
    float s = 0.f;
#pragma unroll
    for (int i = 0; i < 4; i++) {
        int c = tid + i * 128;
        v[i] = xr[c] + rr[c];
        s += v[i];
    }
    __shared__ float red1[4];
    __shared__ float red2[4];
#pragma unroll
    for (int o = 16; o > 0; o >>= 1) s += __shfl_xor_sync(0xffffffffu, s, o);
    if ((tid & 31) == 0) red1[tid >> 5] = s;
    __syncthreads();
    float mu = (red1[0] + red1[1] + red1[2] + red1[3]) * (1.f / (float)DD);

    float q = 0.f;
#pragma unroll
    for (int i = 0; i < 4; i++) {
        float d = v[i] - mu;
        q += d * d;
    }
#pragma unroll
    for (int o = 16; o > 0; o >>= 1) q += __shfl_xor_sync(0xffffffffu, q, o);
    if ((tid & 31) == 0) red2[tid >> 5] = q;
    __syncthreads();
    float var = (red2[0] + red2[1] + red2[2] + red2[3]) * (1.f / (float)DD);
    float rstd = rsqrtf(var + 1e-5f);
#pragma unroll
    for (int i = 0; i < 4; i++) {
        int c = tid + i * 128;
        float o = (v[i] - mu) * rstd * g[c] + be[c];
        xr[c] = o;
        hr[c] = __float2half(o);
    }
}

// ---------------------------------------------------------------------------
// Head projection: out[M,N] = A[M,K] @ W[K,N] + bias, N<=6, K<=256.
// W cached in SMEM; one row per thread, float4 A loads.
// ---------------------------------------------------------------------------
template <int N>
__global__ void __launch_bounds__(256) head_kernel(
    const float* __restrict__ A, const float* __restrict__ W,
    const float* __restrict__ bias, float* __restrict__ out, int M, int K)
{
    __shared__ float ws[256 * N];
    for (int i = threadIdx.x; i < K * N; i += 256) ws[i] = W[i];
    __syncthreads();
    int m = blockIdx.x * 256 + threadIdx.x;
    if (m >= M) return;
    const float4* a = (const float4*)(A + (size_t)m * K);
    float acc[N];
#pragma unroll
    for (int n = 0; n < N; n++) acc[n] = bias[n];
    for (int k4 = 0; k4 < K / 4; k4++) {
        float4 av = a[k4];
#pragma unroll
        for (int n = 0; n < N; n++) {
            acc[n] += av.x * ws[(k4 * 4 + 0) * N + n];
            acc[n] += av.y * ws[(k4 * 4 + 1) * N + n];
            acc[n] += av.z * ws[(k4 * 4 + 2) * N + n];
            acc[n] += av.w * ws[(k4 * 4 + 3) * N + n];
        }
    }
#pragma unroll
    for (int n = 0; n < N; n++) out[(size_t)m * N + n] = acc[n];
}

// ---------------------------------------------------------------------------
// Host launcher
// ---------------------------------------------------------------------------
extern "C" void kernel_launch(void* const* d_in, const int* in_sizes, int n_in,
                              void* d_out, int out_size)
{
    const float* z_style   = (const float*)d_in[0];
    const float* z_skill   = (const float*)d_in[1];
    const float* W_lat     = (const float*)d_in[2];
    const float* b_lat     = (const float*)d_in[3];
    const float* temp_bias = (const float*)d_in[4];
    const float* Wq  = (const float*)d_in[5];
    const float* bq  = (const float*)d_in[6];
    const float* Wk  = (const float*)d_in[7];
    const float* bk  = (const float*)d_in[8];
    const float* Wv  = (const float*)d_in[9];
    const float* bv  = (const float*)d_in[10];
    const float* Wo  = (const float*)d_in[11];
    const float* bo  = (const float*)d_in[12];
    const float* g1  = (const float*)d_in[13];
    const float* be1 = (const float*)d_in[14];
    const float* g2  = (const float*)d_in[15];
    const float* be2 = (const float*)d_in[16];
    const float* W1  = (const float*)d_in[17];
    const float* bf1 = (const float*)d_in[18];
    const float* W2  = (const float*)d_in[19];
    const float* bf2 = (const float*)d_in[20];
    const float* Wp1 = (const float*)d_in[21];
    const float* bp1 = (const float*)d_in[22];
    const float* Wp2 = (const float*)d_in[23];
    const float* bp2 = (const float*)d_in[24];
    const float* Ws1 = (const float*)d_in[25];
    const float* bs1 = (const float*)d_in[26];
    const float* Ws2 = (const float*)d_in[27];
    const float* bs2 = (const float*)d_in[28];
    float* out = (float*)d_out;

    float *x, *tmp, *t1, *s1, *bqkv;
    __half *z16, *x16, *qkv16, *ctx16, *h116;
    __half *wqkvT, *woT, *w1T, *w2T, *wlatT, *wp1T, *ws1T;
    cudaGetSymbolAddress((void**)&x,     g_x);
    cudaGetSymbolAddress((void**)&tmp,   g_tmp);
    cudaGetSymbolAddress((void**)&t1,    g_t1);
    cudaGetSymbolAddress((void**)&s1,    g_s1);
    cudaGetSymbolAddress((void**)&bqkv,  g_bqkv);
    cudaGetSymbolAddress((void**)&z16,   g_z16);
    cudaGetSymbolAddress((void**)&x16,   g_x16);
    cudaGetSymbolAddress((void**)&qkv16, g_qkv16);
    cudaGetSymbolAddress((void**)&ctx16, g_ctx16);
    cudaGetSymbolAddress((void**)&h116,  g_h116);
    cudaGetSymbolAddress((void**)&wqkvT, g_wqkvT);
    cudaGetSymbolAddress((void**)&woT,   g_woT);
    cudaGetSymbolAddress((void**)&w1T,   g_w1T);
    cudaGetSymbolAddress((void**)&w2T,   g_w2T);
    cudaGetSymbolAddress((void**)&wlatT, g_wlatT);
    cudaGetSymbolAddress((void**)&wp1T,  g_wp1T);
    cudaGetSymbolAddress((void**)&ws1T,  g_ws1T);

    cudaFuncSetAttribute(hgemm_kernel<0,1>, cudaFuncAttributeMaxDynamicSharedMemorySize, GSMEM);
    cudaFuncSetAttribute(hgemm_kernel<0,2>, cudaFuncAttributeMaxDynamicSharedMemorySize, GSMEM);
    cudaFuncSetAttribute(hgemm_kernel<1,1>, cudaFuncAttributeMaxDynamicSharedMemorySize, GSMEM);
    cudaFuncSetAttribute(hgemm_kernel<1,2>, cudaFuncAttributeMaxDynamicSharedMemorySize, GSMEM);
    cudaFuncSetAttribute(attn_mma_kernel, cudaFuncAttributeMaxDynamicSharedMemorySize, ASMEM);

    const dim3 tb(32, 8);
    transp_kernel<<<dim3(16, 16, LL), tb>>>(Wq, wqkvT,                   DD, DD, (size_t)DD*DD, (size_t)3*DD*DD);
    transp_kernel<<<dim3(16, 16, LL), tb>>>(Wk, wqkvT + (size_t)DD*DD,   DD, DD, (size_t)DD*DD, (size_t)3*DD*DD);
    transp_kernel<<<dim3(16, 16, LL), tb>>>(Wv, wqkvT + (size_t)2*DD*DD, DD, DD, (size_t)DD*DD, (size_t)3*DD*DD);
    transp_kernel<<<dim3(16, 16, LL), tb>>>(Wo, woT,  DD, DD,  (size_t)DD*DD,  (size_t)DD*DD);
    transp_kernel<<<dim3(64, 16, LL), tb>>>(W1, w1T,  DD, DFF, (size_t)DD*DFF, (size_t)DFF*DD);
    transp_kernel<<<dim3(16, 64, LL), tb>>>(W2, w2T,  DFF, DD, (size_t)DFF*DD, (size_t)DD*DFF);
    transp_kernel<<<dim3((DD*SS)/32, LAT/32, 1), tb>>>(W_lat, wlatT, LAT, DD*SS, 0, 0);
    transp_kernel<<<dim3((DD/2)/32, DD/32, 1),  tb>>>(Wp1, wp1T, DD, DD/2, 0, 0);
    transp_kernel<<<dim3((DD/2)/32, LAT/32, 1), tb>>>(Ws1, ws1T, LAT, DD/2, 0, 0);

    concat_z_kernel<<<(BB * LAT + 255) / 256, 256>>>(z_style, z_skill, z16);
    concat_bqkv_kernel<<<(LL * 3 * DD + 255) / 256, 256>>>(bq, bk, bv, bqkv);

    hgemm_kernel<1,1><<<dim3((DD*SS)/128, 1), 256, GSMEM>>>(
        BB, DD*SS, LAT, z16, wlatT, b_lat, x, nullptr);
    add_pe_kernel<<<(NTOK * DD + 255) / 256, 256>>>(x, x16);

    for (int l = 0; l < LL; l++) {
        const __half* wqkv_l = wqkvT + (size_t)l * 3 * DD * DD;
        const __half* wo_l   = woT   + (size_t)l * DD * DD;
        const __half* w1_l   = w1T   + (size_t)l * DFF * DD;
        const __half* w2_l   = w2T   + (size_t)l * DD * DFF;

        hgemm_kernel<0,2><<<dim3(12, NTOK/128), 256, GSMEM>>>(
            NTOK, 3*DD, DD, x16, wqkv_l, bqkv + (size_t)l*3*DD, nullptr, qkv16);

        attn_mma_kernel<<<dim3(4, HH, BB), 256, ASMEM>>>(qkv16, temp_bias, ctx16);

        hgemm_kernel<0,1><<<dim3(4, NTOK/128), 256, GSMEM>>>(
            NTOK, DD, DD, ctx16, wo_l, bo + (size_t)l*DD, tmp, nullptr);
        ln_kernel<<<NTOK, 128>>>(x, tmp, g1 + l*DD, be1 + l*DD, x16);

        hgemm_kernel<1,2><<<dim3(16, NTOK/128), 256, GSMEM>>>(
            NTOK, DFF, DD, x16, w1_l, bf1 + (size_t)l*DFF, nullptr, h116);
        hgemm_kernel<0,1><<<dim3(4, NTOK/128), 256, GSMEM>>>(
            NTOK, DD, DFF, h116, w2_l, bf2 + (size_t)l*DD, tmp, nullptr);
        ln_kernel<<<NTOK, 128>>>(x, tmp, g2 + l*DD, be2 + l*DD, x16);
    }

    hgemm_kernel<1,1><<<dim3((DD/2)/128, NTOK/128), 256, GSMEM>>>(
        NTOK, DD/2, DD, x16, wp1T, bp1, t1, nullptr);
    head_kernel<OUTD><<<(NTOK + 255) / 256, 256>>>(
        t1, Wp2, bp2, out, NTOK, DD/2);

    hgemm_kernel<1,1><<<dim3((DD/2)/128, 1), 256, GSMEM>>>(
        BB, DD/2, LAT, z16, ws1T, bs1, s1, nullptr);
    head_kernel<5><<<(BB + 255) / 256, 256>>>(
        s1, Ws2, bs2, out + (size_t)NTOK * OUTD, BB, DD/2);
}